// round 15
// baseline (speedup 1.0000x reference)
#include <cuda_runtime.h>
#include <cuda_fp16.h>
#include <mma.h>
#include <math.h>

using namespace nvcuda;

#define BATCH 1024
#define T     127
#define ENC   256
#define DEC   256

// ---------------- scratch (device globals) ----------------------------------
__device__ __half g_Ueh[(size_t)BATCH * T * ENC];   // 66.6 MB (streamed)
__device__ __half g_Xh[(size_t)BATCH * T * ENC];    // 66.6 MB (L2-resident)
__device__ __half g_Wh[ENC * ENC];                  // W_Ud fp16
__device__ __half g_Wdhs_h[ENC * 2 * DEC];          // W_dhs fp16 (256x512)
__device__ __half g_Whh_h[4 * DEC * DEC];           // W_hh fp16 (1024x256)
__device__ float  g_h[2][BATCH * DEC];
__device__ float  g_c[2][BATCH * DEC];
__device__ __half g_hh[BATCH * DEC];                // fp16 copy of current h
__device__ __half g_ch[BATCH * DEC];                // fp16 copy of current c
__device__ float  g_Wd[BATCH * ENC];                // bias-folded Wd
__device__ float  g_gates[(size_t)BATCH * 4 * DEC];
__device__ float  g_ctx[BATCH * ENC];

__device__ __forceinline__ __half2 fast_tanh2(__half2 x) {
    return h2tanh_approx(x);
}

// ---------------- fused init: weight converts + state zero -------------------
// index ranges: [0,65536) Wh | [65536,196608) Wdhs | [196608,458752) Whh |
//               [458752,720896) state zero
__global__ __launch_bounds__(256) void k_init(
    const float* __restrict__ Wud, const float* __restrict__ Wdhs,
    const float* __restrict__ Whh)
{
    int i = blockIdx.x * 256 + threadIdx.x;
    if (i < 65536) {
        g_Wh[i] = __float2half(Wud[i]);
    } else if (i < 196608) {
        int j = i - 65536;
        g_Wdhs_h[j] = __float2half(Wdhs[j]);
    } else if (i < 458752) {
        int j = i - 196608;
        g_Whh_h[j] = __float2half(Whh[j]);
    } else {
        int j = i - 458752;
        g_h[0][j] = 0.f;
        g_c[0][j] = 0.f;
        g_hh[j] = __float2half(0.f);
        g_ch[j] = __float2half(0.f);
    }
}

// ---------------- X fp32 -> fp16 ---------------------------------------------
__global__ __launch_bounds__(256) void k_convert_x(const float* __restrict__ X) {
    size_t i = ((size_t)blockIdx.x * 256 + threadIdx.x) * 4;
    float4 v = *(const float4*)(X + i);
    *(__half2*)(g_Xh + i)     = __floats2half2_rn(v.x, v.y);
    *(__half2*)(g_Xh + i + 2) = __floats2half2_rn(v.z, v.w);
}

// ---------------- Ue GEMM: wmma with direct-global fragment loads ------------
// 64x64 tile, 8 warps (4m x 2n), each warp 16x32. A: g_Xh row-major ld 256.
// B: g_Wh [N][K] row-major == matrix_b col-major ld 256.
__global__ __launch_bounds__(256) void k_ue_wmma(const float* __restrict__ bias)
{
    __shared__ float cs[64][68];
    int tid = threadIdx.x;
    int warp = tid >> 5;
    int wm = warp >> 1, wn = warp & 1;
    size_t m0 = (size_t)blockIdx.y * 64;
    int n0 = blockIdx.x * 64;

    wmma::fragment<wmma::accumulator, 16, 16, 16, float> cfrag[2];
    wmma::fill_fragment(cfrag[0], 0.f);
    wmma::fill_fragment(cfrag[1], 0.f);

    const __half* abase = g_Xh + (m0 + wm * 16) * 256;
    const __half* bbase0 = g_Wh + (size_t)(n0 + wn * 32) * 256;
    const __half* bbase1 = g_Wh + (size_t)(n0 + wn * 32 + 16) * 256;

    #pragma unroll
    for (int k = 0; k < 256; k += 16) {
        wmma::fragment<wmma::matrix_a, 16, 16, 16, __half, wmma::row_major> afrag;
        wmma::load_matrix_sync(afrag, abase + k, 256);
        wmma::fragment<wmma::matrix_b, 16, 16, 16, __half, wmma::col_major> bfrag;
        wmma::load_matrix_sync(bfrag, bbase0 + k, 256);
        wmma::mma_sync(cfrag[0], afrag, bfrag, cfrag[0]);
        wmma::load_matrix_sync(bfrag, bbase1 + k, 256);
        wmma::mma_sync(cfrag[1], afrag, bfrag, cfrag[1]);
    }

    wmma::store_matrix_sync(&cs[wm * 16][wn * 32],      cfrag[0], 68, wmma::mem_row_major);
    wmma::store_matrix_sync(&cs[wm * 16][wn * 32 + 16], cfrag[1], 68, wmma::mem_row_major);
    __syncthreads();

    int r = tid >> 2, c0 = (tid & 3) * 16;
    size_t m = m0 + r;
    __half2* dst = (__half2*)(g_Ueh + m * 256 + n0 + c0);
    #pragma unroll
    for (int j = 0; j < 16; j += 2) {
        float v0 = cs[r][c0 + j]     + bias[n0 + c0 + j];
        float v1 = cs[r][c0 + j + 1] + bias[n0 + c0 + j + 1];
        __stcs(dst + (j >> 1), __floats2half2_rn(v0, v1));   // Ue: evict-first
    }
}

// ---------------- Wd + gates: wmma with direct-global fragment loads ---------
// blocks [0,64): Wd (M=1024,N=256,K=512; A=[h|c] fp16). blocks [64,320): gates.
__global__ __launch_bounds__(256) void k_wd_gates(
    const float* __restrict__ bdhs,
    const float* __restrict__ bih, const float* __restrict__ bhh)
{
    __shared__ float cs[64][68];
    int tid = threadIdx.x;
    int warp = tid >> 5;
    int wm = warp >> 1, wn = warp & 1;
    int bid = blockIdx.x;

    int m0, n0, K, ldw;
    const __half* Wsrc;
    bool is_wd = (bid < 64);
    if (is_wd) {
        m0 = (bid >> 2) * 64;
        n0 = (bid & 3) * 64;
        K = 512;  ldw = 512;  Wsrc = g_Wdhs_h;
    } else {
        int rem = bid - 64;
        m0 = (rem >> 4) * 64;
        n0 = (rem & 15) * 64;
        K = 256;  ldw = 256;  Wsrc = g_Whh_h;
    }

    wmma::fragment<wmma::accumulator, 16, 16, 16, float> cfrag[2];
    wmma::fill_fragment(cfrag[0], 0.f);
    wmma::fill_fragment(cfrag[1], 0.f);

    const __half* bbase0 = Wsrc + (size_t)(n0 + wn * 32) * ldw;
    const __half* bbase1 = Wsrc + (size_t)(n0 + wn * 32 + 16) * ldw;

    for (int k = 0; k < K; k += 16) {
        // A: h for k<256, c for k>=256 (wd only)
        const __half* abase = (k < 256)
            ? (g_hh + (size_t)(m0 + wm * 16) * 256 + k)
            : (g_ch + (size_t)(m0 + wm * 16) * 256 + (k - 256));
        wmma::fragment<wmma::matrix_a, 16, 16, 16, __half, wmma::row_major> afrag;
        wmma::load_matrix_sync(afrag, abase, 256);
        wmma::fragment<wmma::matrix_b, 16, 16, 16, __half, wmma::col_major> bfrag;
        wmma::load_matrix_sync(bfrag, bbase0 + k, ldw);
        wmma::mma_sync(cfrag[0], afrag, bfrag, cfrag[0]);
        wmma::load_matrix_sync(bfrag, bbase1 + k, ldw);
        wmma::mma_sync(cfrag[1], afrag, bfrag, cfrag[1]);
    }

    wmma::store_matrix_sync(&cs[wm * 16][wn * 32],      cfrag[0], 68, wmma::mem_row_major);
    wmma::store_matrix_sync(&cs[wm * 16][wn * 32 + 16], cfrag[1], 68, wmma::mem_row_major);
    __syncthreads();

    int r = tid >> 2, c0 = (tid & 3) * 16;
    int m = m0 + r;
    if (is_wd) {
        #pragma unroll
        for (int j = 0; j < 16; j++) {
            int n = n0 + c0 + j;
            g_Wd[m * 256 + n] = cs[r][c0 + j] + bdhs[n];
        }
    } else {
        #pragma unroll
        for (int j = 0; j < 16; j++) {
            int n = n0 + c0 + j;
            g_gates[(size_t)m * 1024 + n] = cs[r][c0 + j] + bih[n] + bhh[n];
        }
    }
}

// ---------------- fused one-pass attention + LSTM cell -----------------------
__global__ __launch_bounds__(256) void k_attn_cell(
    const float* __restrict__ Wvd, const float* __restrict__ bvd,
    const float* __restrict__ Ww,  const float* __restrict__ bw,
    const float* __restrict__ yhist,
    const float* __restrict__ Wih, int step, int cur)
{
    int b = blockIdx.x;
    int tid = threadIdx.x, lane = tid & 31, warp = tid >> 5;
    __shared__ float s_wdf[256];
    __shared__ float s_red[8][264];
    __shared__ float s_part[8];
    __shared__ float s_bcast;

    s_wdf[tid] = g_Wd[b * 256 + tid];       // bias already folded
    __syncthreads();

    int e0 = lane * 8;
    __half2 wdh[4];
    float wvr[8];
    #pragma unroll
    for (int j = 0; j < 4; j++)
        wdh[j] = __floats2half2_rn(s_wdf[e0 + 2 * j], s_wdf[e0 + 2 * j + 1]);
    #pragma unroll
    for (int j = 0; j < 8; j++) wvr[j] = Wvd[e0 + j];

    const __half* ue = g_Ueh + (size_t)b * T * ENC;
    const __half* xb = g_Xh + (size_t)b * T * ENC;
    float bv = bvd[0];

    float ctx[8] = {};
    float sumexp = 0.f;

    #pragma unroll
    for (int g = 0; g < 4; g++) {
        float acc[4];
        float4 xraw[4];
        {
            float4 uraw[4];
            #pragma unroll
            for (int u = 0; u < 4; u++) {
                int t = warp + (g * 4 + u) * 8;
                int te = t < T ? t : 0;
                uraw[u] = __ldcs((const float4*)(ue + te * 256 + e0));  // stream Ue
            }
            #pragma unroll
            for (int u = 0; u < 4; u++) {
                int t = warp + (g * 4 + u) * 8;
                int te = t < T ? t : 0;
                xraw[u] = *(const float4*)(xb + te * 256 + e0);         // X: resident
            }
            #pragma unroll
            for (int u = 0; u < 4; u++) {
                const __half2* up = (const __half2*)&uraw[u];
                float a = 0.f;
                #pragma unroll
                for (int j = 0; j < 4; j++) {
                    __half2 th = fast_tanh2(__hadd2(wdh[j], up[j]));
                    float2 f = __half22float2(th);
                    a = fmaf(f.x, wvr[2 * j],     a);
                    a = fmaf(f.y, wvr[2 * j + 1], a);
                }
                acc[u] = a;
            }
        }
        #pragma unroll
        for (int o = 16; o; o >>= 1) {
            #pragma unroll
            for (int u = 0; u < 4; u++)
                acc[u] += __shfl_xor_sync(0xffffffffu, acc[u], o);
        }
        float ew[4];
        #pragma unroll
        for (int u = 0; u < 4; u++) {
            int t = warp + (g * 4 + u) * 8;
            ew[u] = (t < T) ? __expf(acc[u] + bv) : 0.f;
            sumexp += ew[u];
        }
        #pragma unroll
        for (int u = 0; u < 4; u++) {
            const __half2* xp = (const __half2*)&xraw[u];
            #pragma unroll
            for (int j = 0; j < 4; j++) {
                float2 f = __half22float2(xp[j]);
                ctx[2 * j]     = fmaf(ew[u], f.x, ctx[2 * j]);
                ctx[2 * j + 1] = fmaf(ew[u], f.y, ctx[2 * j + 1]);
            }
        }
    }
    #pragma unroll
    for (int j = 0; j < 8; j++) s_red[warp][e0 + j] = ctx[j];
    if (lane == 0) s_part[warp] = sumexp;
    __syncthreads();
    if (tid == 0) {
        float ss = 0.f;
        #pragma unroll
        for (int i = 0; i < 8; i++) ss += s_part[i];
        s_bcast = ss;
    }
    __syncthreads();
    float inv = 1.f / s_bcast;

    float cv = 0.f;
    #pragma unroll
    for (int g = 0; g < 8; g++) cv += s_red[g][tid];
    cv *= inv;
    g_ctx[b * 256 + tid] = cv;

    float yv = cv * Ww[tid];
    #pragma unroll
    for (int o = 16; o; o >>= 1) yv += __shfl_xor_sync(0xffffffffu, yv, o);
    if (lane == 0) s_part[warp] = yv;
    __syncthreads();
    if (tid == 0) {
        float ss = 0.f;
        #pragma unroll
        for (int i = 0; i < 8; i++) ss += s_part[i];
        s_bcast = ss + yhist[b * T + step] * Ww[256] + bw[0];
    }
    __syncthreads();
    float yt = s_bcast;

    // LSTM cell for row b, d = tid — fp32 recurrence, fp16 copies for GEMMs
    const float* gb = g_gates + (size_t)b * 1024;
    float gi = gb[tid]       + yt * Wih[tid];
    float gf = gb[256 + tid] + yt * Wih[256 + tid];
    float gg = gb[512 + tid] + yt * Wih[512 + tid];
    float go = gb[768 + tid] + yt * Wih[768 + tid];
    float ig = 1.f / (1.f + expf(-gi));
    float fg = 1.f / (1.f + expf(-gf));
    float gt = tanhf(gg);
    float og = 1.f / (1.f + expf(-go));
    int nxt = cur ^ 1;
    int idx = b * 256 + tid;
    float cn = fg * g_c[cur][idx] + ig * gt;
    float hn = og * tanhf(cn);
    g_c[nxt][idx] = cn;
    g_h[nxt][idx] = hn;
    g_ch[idx] = __float2half(cn);
    g_hh[idx] = __float2half(hn);
}

// ---------------- final projection -------------------------------------------
__global__ __launch_bounds__(256) void k_final(
    const float* __restrict__ Wfc, const float* __restrict__ bfc,
    float* __restrict__ out, int fin)
{
    int b = blockIdx.x, tid = threadIdx.x, lane = tid & 31, warp = tid >> 5;
    __shared__ float s_part[8];
    float v = g_h[fin][b * 256 + tid] * Wfc[tid]
            + g_ctx[b * 256 + tid] * Wfc[256 + tid];
    #pragma unroll
    for (int o = 16; o; o >>= 1) v += __shfl_xor_sync(0xffffffffu, v, o);
    if (lane == 0) s_part[warp] = v;
    __syncthreads();
    if (tid == 0) {
        float ss = 0.f;
        #pragma unroll
        for (int i = 0; i < 8; i++) ss += s_part[i];
        out[b] = ss + bfc[0];
    }
}

// ---------------- host -------------------------------------------------------
extern "C" void kernel_launch(void* const* d_in, const int* in_sizes, int n_in,
                              void* d_out, int out_size)
{
    const float* X     = (const float*)d_in[0];
    const float* yhist = (const float*)d_in[1];
    const float* W_vd  = (const float*)d_in[2];
    const float* b_vd  = (const float*)d_in[3];
    const float* W_dhs = (const float*)d_in[4];
    const float* b_dhs = (const float*)d_in[5];
    const float* W_Ud  = (const float*)d_in[6];
    const float* b_Ud  = (const float*)d_in[7];
    const float* W_w   = (const float*)d_in[8];
    const float* b_w   = (const float*)d_in[9];
    const float* W_ih  = (const float*)d_in[10];
    const float* W_hh  = (const float*)d_in[11];
    const float* b_ih  = (const float*)d_in[12];
    const float* b_hh  = (const float*)d_in[13];
    const float* W_fc  = (const float*)d_in[14];
    const float* b_fc  = (const float*)d_in[15];
    float* out = (float*)d_out;

    k_init<<<720896 / 256, 256>>>(W_Ud, W_dhs, W_hh);
    k_convert_x<<<((size_t)BATCH * T * ENC) / 4 / 256, 256>>>(X);
    {
        dim3 grid(ENC / 64, (BATCH * T) / 64);
        k_ue_wmma<<<grid, 256>>>(b_Ud);
    }

    for (int s = 0; s < T; s++) {
        int cur = s & 1;
        k_wd_gates<<<320, 256>>>(b_dhs, b_ih, b_hh);
        k_attn_cell<<<BATCH, 256>>>(W_vd, b_vd, W_w, b_w, yhist, W_ih, s, cur);
    }

    k_final<<<BATCH, 256>>>(W_fc, b_fc, out, T & 1);
}

// round 16
// speedup vs baseline: 1.5340x; 1.5340x over previous
#include <cuda_runtime.h>
#include <cuda_fp16.h>
#include <mma.h>
#include <math.h>

using namespace nvcuda;

#define BATCH 1024
#define T     127
#define ENC   256
#define DEC   256

// ---------------- scratch (device globals) ----------------------------------
__device__ __half g_Ueh[(size_t)BATCH * T * ENC];   // 66.6 MB (streamed)
__device__ __half g_Xh[(size_t)BATCH * T * ENC];    // 66.6 MB (L2-resident)
__device__ __half g_Wh[ENC * ENC];                  // W_Ud fp16
__device__ __half g_Wdhs_h[ENC * 2 * DEC];          // W_dhs fp16 (256x512)
__device__ __half g_Whh_h[4 * DEC * DEC];           // W_hh fp16 (1024x256)
__device__ float  g_h[2][BATCH * DEC];
__device__ float  g_c[2][BATCH * DEC];
__device__ __half g_hh[BATCH * DEC];                // fp16 copy of current h
__device__ __half g_ch[BATCH * DEC];                // fp16 copy of current c
__device__ float  g_Wd[BATCH * ENC];                // bias-folded Wd
__device__ float  g_gates[(size_t)BATCH * 4 * DEC];
__device__ float  g_ctx[BATCH * ENC];

__device__ __forceinline__ __half2 fast_tanh2(__half2 x) {
    return h2tanh_approx(x);
}

// ---------------- fused init: weight converts + state zero -------------------
__global__ __launch_bounds__(256) void k_init(
    const float* __restrict__ Wud, const float* __restrict__ Wdhs,
    const float* __restrict__ Whh)
{
    int i = blockIdx.x * 256 + threadIdx.x;
    if (i < 65536) {
        g_Wh[i] = __float2half(Wud[i]);
    } else if (i < 196608) {
        int j = i - 65536;
        g_Wdhs_h[j] = __float2half(Wdhs[j]);
    } else if (i < 458752) {
        int j = i - 196608;
        g_Whh_h[j] = __float2half(Whh[j]);
    } else {
        int j = i - 458752;
        g_h[0][j] = 0.f;
        g_c[0][j] = 0.f;
        g_hh[j] = __float2half(0.f);
        g_ch[j] = __float2half(0.f);
    }
}

// ---------------- X fp32 -> fp16 ---------------------------------------------
__global__ __launch_bounds__(256) void k_convert_x(const float* __restrict__ X) {
    size_t i = ((size_t)blockIdx.x * 256 + threadIdx.x) * 4;
    float4 v = *(const float4*)(X + i);
    *(__half2*)(g_Xh + i)     = __floats2half2_rn(v.x, v.y);
    *(__half2*)(g_Xh + i + 2) = __floats2half2_rn(v.z, v.w);
}

// ---------------- Ue GEMM via fp16 wmma (smem-staged operands) ----------------
__global__ __launch_bounds__(256) void k_ue_wmma(const float* __restrict__ bias)
{
    __shared__ __half sA[64][136];
    __shared__ __half sB[64][136];
    int tid = threadIdx.x;
    int warp = tid >> 5;
    int wm = warp >> 1, wn = warp & 1;
    size_t m0 = (size_t)blockIdx.y * 64;
    int n0 = blockIdx.x * 64;

    wmma::fragment<wmma::accumulator, 16, 16, 16, float> cfrag[2];
    wmma::fill_fragment(cfrag[0], 0.f);
    wmma::fill_fragment(cfrag[1], 0.f);

    for (int kc = 0; kc < 256; kc += 128) {
        #pragma unroll
        for (int i = 0; i < 4; i++) {
            int lin = tid + i * 256;
            int r = lin >> 4, cb = lin & 15;
            *(float4*)&sA[r][cb * 8] =
                *(const float4*)(g_Xh + (m0 + r) * 256 + kc + cb * 8);
        }
        #pragma unroll
        for (int i = 0; i < 4; i++) {
            int lin = tid + i * 256;
            int r = lin >> 4, cb = lin & 15;
            *(float4*)&sB[r][cb * 8] =
                *(const float4*)(g_Wh + (size_t)(n0 + r) * 256 + kc + cb * 8);
        }
        __syncthreads();
        #pragma unroll
        for (int k = 0; k < 128; k += 16) {
            wmma::fragment<wmma::matrix_a, 16, 16, 16, __half, wmma::row_major> afrag;
            wmma::load_matrix_sync(afrag, &sA[wm * 16][k], 136);
            #pragma unroll
            for (int j = 0; j < 2; j++) {
                wmma::fragment<wmma::matrix_b, 16, 16, 16, __half, wmma::col_major> bfrag;
                wmma::load_matrix_sync(bfrag, &sB[wn * 32 + j * 16][k], 136);
                wmma::mma_sync(cfrag[j], afrag, bfrag, cfrag[j]);
            }
        }
        __syncthreads();
    }

    float* cs = (float*)&sA[0][0];
    wmma::store_matrix_sync(cs + (wm * 16) * 68 + wn * 32,      cfrag[0], 68, wmma::mem_row_major);
    wmma::store_matrix_sync(cs + (wm * 16) * 68 + wn * 32 + 16, cfrag[1], 68, wmma::mem_row_major);
    __syncthreads();

    int r = tid >> 2, c0 = (tid & 3) * 16;
    size_t m = m0 + r;
    __half2* dst = (__half2*)(g_Ueh + m * 256 + n0 + c0);
    #pragma unroll
    for (int j = 0; j < 16; j += 2) {
        float v0 = cs[r * 68 + c0 + j]     + bias[n0 + c0 + j];
        float v1 = cs[r * 68 + c0 + j + 1] + bias[n0 + c0 + j + 1];
        __stcs(dst + (j >> 1), __floats2half2_rn(v0, v1));   // Ue: evict-first
    }
}

// ---------------- Wd + gates via fp16 wmma (smem-staged operands) -------------
// blocks [0,64): Wd tiles (M=1024,N=256,K=512; A = [h|c] fp16, full K per block)
// blocks [64,320): gates tiles (M=1024,N=1024,K=256; A = h fp16)
__global__ __launch_bounds__(256) void k_wd_gates(
    const float* __restrict__ bdhs,
    const float* __restrict__ bih, const float* __restrict__ bhh)
{
    __shared__ union {
        struct { __half A[64][72]; __half B[64][72]; } h;
        float C[64][68];
    } sm;
    int tid = threadIdx.x;
    int warp = tid >> 5;
    int wm = warp >> 1, wn = warp & 1;
    int bid = blockIdx.x;

    int m0, n0, nk, ldw;
    const __half* Wsrc;
    bool is_wd = (bid < 64);
    if (is_wd) {
        m0 = (bid >> 2) * 64;
        n0 = (bid & 3) * 64;
        nk = 8;  ldw = 512;  Wsrc = g_Wdhs_h;
    } else {
        int rem = bid - 64;
        m0 = (rem >> 4) * 64;
        n0 = (rem & 15) * 64;
        nk = 4;  ldw = 256;  Wsrc = g_Whh_h;
    }

    wmma::fragment<wmma::accumulator, 16, 16, 16, float> cfrag[2];
    wmma::fill_fragment(cfrag[0], 0.f);
    wmma::fill_fragment(cfrag[1], 0.f);

    for (int c = 0; c < nk; c++) {
        int kc = c * 64;
        const __half* Asrc = (kc < 256) ? g_hh : g_ch;
        int kof = (kc < 256) ? kc : (kc - 256);
        #pragma unroll
        for (int i = 0; i < 2; i++) {
            int lin = tid + i * 256;
            int r = lin >> 3, cb = lin & 7;
            *(float4*)&sm.h.A[r][cb * 8] =
                *(const float4*)(Asrc + (size_t)(m0 + r) * 256 + kof + cb * 8);
        }
        #pragma unroll
        for (int i = 0; i < 2; i++) {
            int lin = tid + i * 256;
            int r = lin >> 3, cb = lin & 7;
            *(float4*)&sm.h.B[r][cb * 8] =
                *(const float4*)(Wsrc + (size_t)(n0 + r) * ldw + kc + cb * 8);
        }
        __syncthreads();
        #pragma unroll
        for (int k = 0; k < 64; k += 16) {
            wmma::fragment<wmma::matrix_a, 16, 16, 16, __half, wmma::row_major> afrag;
            wmma::load_matrix_sync(afrag, &sm.h.A[wm * 16][k], 72);
            #pragma unroll
            for (int j = 0; j < 2; j++) {
                wmma::fragment<wmma::matrix_b, 16, 16, 16, __half, wmma::col_major> bfrag;
                wmma::load_matrix_sync(bfrag, &sm.h.B[wn * 32 + j * 16][k], 72);
                wmma::mma_sync(cfrag[j], afrag, bfrag, cfrag[j]);
            }
        }
        __syncthreads();
    }

    wmma::store_matrix_sync(&sm.C[wm * 16][wn * 32],      cfrag[0], 68, wmma::mem_row_major);
    wmma::store_matrix_sync(&sm.C[wm * 16][wn * 32 + 16], cfrag[1], 68, wmma::mem_row_major);
    __syncthreads();

    int r = tid >> 2, c0 = (tid & 3) * 16;
    int m = m0 + r;
    if (is_wd) {
        #pragma unroll
        for (int j = 0; j < 16; j++) {
            int n = n0 + c0 + j;
            g_Wd[m * 256 + n] = sm.C[r][c0 + j] + bdhs[n];
        }
    } else {
        #pragma unroll
        for (int j = 0; j < 16; j++) {
            int n = n0 + c0 + j;
            g_gates[(size_t)m * 1024 + n] = sm.C[r][c0 + j] + bih[n] + bhh[n];
        }
    }
}

// ---------------- fused one-pass attention + LSTM cell -----------------------
__global__ __launch_bounds__(256) void k_attn_cell(
    const float* __restrict__ Wvd, const float* __restrict__ bvd,
    const float* __restrict__ Ww,  const float* __restrict__ bw,
    const float* __restrict__ yhist,
    const float* __restrict__ Wih, int step, int cur)
{
    int b = blockIdx.x;
    int tid = threadIdx.x, lane = tid & 31, warp = tid >> 5;
    __shared__ float s_wdf[256];
    __shared__ float s_red[8][264];
    __shared__ float s_part[8];
    __shared__ float s_bcast;

    s_wdf[tid] = g_Wd[b * 256 + tid];       // bias already folded
    __syncthreads();

    int e0 = lane * 8;
    __half2 wdh[4];
    float wvr[8];
    #pragma unroll
    for (int j = 0; j < 4; j++)
        wdh[j] = __floats2half2_rn(s_wdf[e0 + 2 * j], s_wdf[e0 + 2 * j + 1]);
    #pragma unroll
    for (int j = 0; j < 8; j++) wvr[j] = Wvd[e0 + j];

    const __half* ue = g_Ueh + (size_t)b * T * ENC;
    const __half* xb = g_Xh + (size_t)b * T * ENC;
    float bv = bvd[0];

    float ctx[8] = {};
    float sumexp = 0.f;

    #pragma unroll
    for (int g = 0; g < 4; g++) {
        float acc[4];
        float4 xraw[4];
        {
            float4 uraw[4];
            #pragma unroll
            for (int u = 0; u < 4; u++) {
                int t = warp + (g * 4 + u) * 8;
                int te = t < T ? t : 0;
                uraw[u] = __ldcs((const float4*)(ue + te * 256 + e0));  // stream Ue
            }
            #pragma unroll
            for (int u = 0; u < 4; u++) {
                int t = warp + (g * 4 + u) * 8;
                int te = t < T ? t : 0;
                xraw[u] = *(const float4*)(xb + te * 256 + e0);         // X: resident
            }
            #pragma unroll
            for (int u = 0; u < 4; u++) {
                const __half2* up = (const __half2*)&uraw[u];
                float a = 0.f;
                #pragma unroll
                for (int j = 0; j < 4; j++) {
                    __half2 th = fast_tanh2(__hadd2(wdh[j], up[j]));
                    float2 f = __half22float2(th);
                    a = fmaf(f.x, wvr[2 * j],     a);
                    a = fmaf(f.y, wvr[2 * j + 1], a);
                }
                acc[u] = a;
            }
        }
        #pragma unroll
        for (int o = 16; o; o >>= 1) {
            #pragma unroll
            for (int u = 0; u < 4; u++)
                acc[u] += __shfl_xor_sync(0xffffffffu, acc[u], o);
        }
        float ew[4];
        #pragma unroll
        for (int u = 0; u < 4; u++) {
            int t = warp + (g * 4 + u) * 8;
            ew[u] = (t < T) ? __expf(acc[u] + bv) : 0.f;
            sumexp += ew[u];
        }
        #pragma unroll
        for (int u = 0; u < 4; u++) {
            const __half2* xp = (const __half2*)&xraw[u];
            #pragma unroll
            for (int j = 0; j < 4; j++) {
                float2 f = __half22float2(xp[j]);
                ctx[2 * j]     = fmaf(ew[u], f.x, ctx[2 * j]);
                ctx[2 * j + 1] = fmaf(ew[u], f.y, ctx[2 * j + 1]);
            }
        }
    }
    #pragma unroll
    for (int j = 0; j < 8; j++) s_red[warp][e0 + j] = ctx[j];
    if (lane == 0) s_part[warp] = sumexp;
    __syncthreads();
    if (tid == 0) {
        float ss = 0.f;
        #pragma unroll
        for (int i = 0; i < 8; i++) ss += s_part[i];
        s_bcast = ss;
    }
    __syncthreads();
    float inv = 1.f / s_bcast;

    float cv = 0.f;
    #pragma unroll
    for (int g = 0; g < 8; g++) cv += s_red[g][tid];
    cv *= inv;
    g_ctx[b * 256 + tid] = cv;

    float yv = cv * Ww[tid];
    #pragma unroll
    for (int o = 16; o; o >>= 1) yv += __shfl_xor_sync(0xffffffffu, yv, o);
    if (lane == 0) s_part[warp] = yv;
    __syncthreads();
    if (tid == 0) {
        float ss = 0.f;
        #pragma unroll
        for (int i = 0; i < 8; i++) ss += s_part[i];
        s_bcast = ss + yhist[b * T + step] * Ww[256] + bw[0];
    }
    __syncthreads();
    float yt = s_bcast;

    // LSTM cell for row b, d = tid — fp32 recurrence, fp16 copies for GEMMs
    const float* gb = g_gates + (size_t)b * 1024;
    float gi = gb[tid]       + yt * Wih[tid];
    float gf = gb[256 + tid] + yt * Wih[256 + tid];
    float gg = gb[512 + tid] + yt * Wih[512 + tid];
    float go = gb[768 + tid] + yt * Wih[768 + tid];
    float ig = 1.f / (1.f + expf(-gi));
    float fg = 1.f / (1.f + expf(-gf));
    float gt = tanhf(gg);
    float og = 1.f / (1.f + expf(-go));
    int nxt = cur ^ 1;
    int idx = b * 256 + tid;
    float cn = fg * g_c[cur][idx] + ig * gt;
    float hn = og * tanhf(cn);
    g_c[nxt][idx] = cn;
    g_h[nxt][idx] = hn;
    g_ch[idx] = __float2half(cn);
    g_hh[idx] = __float2half(hn);
}

// ---------------- final projection -------------------------------------------
__global__ __launch_bounds__(256) void k_final(
    const float* __restrict__ Wfc, const float* __restrict__ bfc,
    float* __restrict__ out, int fin)
{
    int b = blockIdx.x, tid = threadIdx.x, lane = tid & 31, warp = tid >> 5;
    __shared__ float s_part[8];
    float v = g_h[fin][b * 256 + tid] * Wfc[tid]
            + g_ctx[b * 256 + tid] * Wfc[256 + tid];
    #pragma unroll
    for (int o = 16; o; o >>= 1) v += __shfl_xor_sync(0xffffffffu, v, o);
    if (lane == 0) s_part[warp] = v;
    __syncthreads();
    if (tid == 0) {
        float ss = 0.f;
        #pragma unroll
        for (int i = 0; i < 8; i++) ss += s_part[i];
        out[b] = ss + bfc[0];
    }
}

// ---------------- host -------------------------------------------------------
extern "C" void kernel_launch(void* const* d_in, const int* in_sizes, int n_in,
                              void* d_out, int out_size)
{
    const float* X     = (const float*)d_in[0];
    const float* yhist = (const float*)d_in[1];
    const float* W_vd  = (const float*)d_in[2];
    const float* b_vd  = (const float*)d_in[3];
    const float* W_dhs = (const float*)d_in[4];
    const float* b_dhs = (const float*)d_in[5];
    const float* W_Ud  = (const float*)d_in[6];
    const float* b_Ud  = (const float*)d_in[7];
    const float* W_w   = (const float*)d_in[8];
    const float* b_w   = (const float*)d_in[9];
    const float* W_ih  = (const float*)d_in[10];
    const float* W_hh  = (const float*)d_in[11];
    const float* b_ih  = (const float*)d_in[12];
    const float* b_hh  = (const float*)d_in[13];
    const float* W_fc  = (const float*)d_in[14];
    const float* b_fc  = (const float*)d_in[15];
    float* out = (float*)d_out;

    k_init<<<720896 / 256, 256>>>(W_Ud, W_dhs, W_hh);
    k_convert_x<<<((size_t)BATCH * T * ENC) / 4 / 256, 256>>>(X);
    {
        dim3 grid(ENC / 64, (BATCH * T) / 64);
        k_ue_wmma<<<grid, 256>>>(b_Ud);
    }

    for (int s = 0; s < T; s++) {
        int cur = s & 1;
        k_wd_gates<<<320, 256>>>(b_dhs, b_ih, b_hh);
        k_attn_cell<<<BATCH, 256>>>(W_vd, b_vd, W_w, b_w, yhist, W_ih, s, cur);
    }

    k_final<<<BATCH, 256>>>(W_fc, b_fc, out, T & 1);
}